// round 13
// baseline (speedup 1.0000x reference)
#include <cuda_runtime.h>
#include <cuda_bf16.h>
#include <cstdint>

#define B_   4
#define V_   778
#define F_   1538
#define RW   256
#define NPIX (RW * RW)
#define FARV 10.0f
#define TILE 16
#define NTX  (RW / TILE)   // 16 tiles per axis
#define NTIL (B_ * NTX * NTX)
#define HX   0.05859375f   // 16x16 tile half-extent in NDC (15px span/2 * 2/256)

// ---------------- scratch (static device globals; no allocation) -------------
__device__ float    g_uvz  [B_ * V_ * 3];
__device__ float4   g_e0   [B_ * F_];   // U0,V0,W0,|U0|+|V0|
__device__ float4   g_e1   [B_ * F_];
__device__ float4   g_e2   [B_ * F_];
__device__ float4   g_gi   [B_ * F_];   // Gx,Gy,Gc,-
__device__ float4   g_bbox [B_ * F_];
__device__ int      g_plist[NTIL * F_]; // per-tile partial-tri indices
__device__ int      g_flist[NTIL * F_]; // per-tile full-accept indices
__device__ int      g_np   [NTIL];
__device__ int      g_nf   [NTIL];
__device__ unsigned g_mx   [B_];
__device__ unsigned g_mn   [B_];

// ---------------- K1: project vertices + clear reductions --------------------
__global__ void __launch_bounds__(256) k_project(const float* __restrict__ verts,
                                                 const float* __restrict__ intr,
                                                 const float* __restrict__ R,
                                                 const float* __restrict__ t,
                                                 const float* __restrict__ dist) {
    int idx = blockIdx.x * 256 + threadIdx.x;
    if (idx < B_) { g_mx[idx] = 0u; g_mn[idx] = __float_as_uint(FARV); }
    if (idx >= B_ * V_) return;
    int b = idx / V_;
    const float* p  = verts + idx * 3;
    const float* Rb = R    + b * 9;
    const float* tb = t    + b * 3;
    const float* Kb = intr + b * 9;
    const float* db = dist + b * 5;

    float px = p[0], py = p[1], pz = p[2];
    float x = Rb[0]*px + Rb[1]*py + Rb[2]*pz + tb[0];
    float y = Rb[3]*px + Rb[4]*py + Rb[5]*pz + tb[1];
    float z = Rb[6]*px + Rb[7]*py + Rb[8]*pz + tb[2];

    float zi = z + 1e-9f;
    float x_ = x / zi, y_ = y / zi;
    float k1 = db[0], k2 = db[1], p1 = db[2], p2 = db[3], k3 = db[4];
    float r2 = x_*x_ + y_*y_;
    float radial = 1.0f + k1*r2 + k2*r2*r2 + k3*r2*r2*r2;
    float x2 = x_*radial + 2.0f*p1*x_*y_ + p2*(r2 + 2.0f*x_*x_);
    float y2 = y_*radial + p1*(r2 + 2.0f*y_*y_) + 2.0f*p2*x_*y_;
    float u  = Kb[0]*x2 + Kb[1]*y2 + Kb[2];
    float vv = Kb[3]*x2 + Kb[4]*y2 + Kb[5];
    vv = 256.0f - vv;
    u  = 2.0f * (u  - 128.0f) / 256.0f;
    vv = 2.0f * (vv - 128.0f) / 256.0f;

    g_uvz[idx*3 + 0] = u;
    g_uvz[idx*3 + 1] = vv;
    g_uvz[idx*3 + 2] = z;
}

// ---------------- K2: triangle setup -----------------------------------------
__global__ void __launch_bounds__(256) k_setup(const int* __restrict__ faces) {
    int gid = blockIdx.x * 256 + threadIdx.x;
    if (gid >= B_ * F_) return;
    int b = gid / F_;

    int base = gid * 3;
    int i0 = faces[base + 0], i1 = faces[base + 1], i2 = faces[base + 2];

    const float* va = g_uvz + (b * V_ + i0) * 3;
    const float* vb = g_uvz + (b * V_ + i1) * 3;
    const float* vc = g_uvz + (b * V_ + i2) * 3;
    float ax = va[0], ay = va[1], az = va[2];
    float bx = vb[0], by = vb[1], bz = vb[2];
    float cx = vc[0], cy = vc[1], cz = vc[2];

    float den = (bx - ax) * (cy - ay) - (by - ay) * (cx - ax);
    bool ok = (fabsf(den) > 1e-8f) && (az > 1e-8f) && (bz > 1e-8f) && (cz > 1e-8f);

    float4 e0, e1, e2, gi, bb;
    if (!ok) {
        e0 = make_float4(0.f, 0.f, -1e30f, 0.f);
        e1 = make_float4(0.f, 0.f, 0.f, 0.f);
        e2 = make_float4(0.f, 0.f, 0.f, 0.f);
        gi = make_float4(0.f, 0.f, 0.f, 0.f);
        bb = make_float4(2e30f, -2e30f, 2e30f, -2e30f);
    } else {
        float id = 1.0f / den;
        float U0 = (by - cy) * id, V0 = (cx - bx) * id;
        float W0 = -(U0 * cx + V0 * cy);
        float U1 = (cy - ay) * id, V1 = (ax - cx) * id;
        float W1 = -(U1 * cx + V1 * cy);
        float U2 = -(U0 + U1), V2 = -(V0 + V1), W2 = 1.0f - W0 - W1;
        float ra = 1.0f / az, rb = 1.0f / bz, rc = 1.0f / cz;
        float dA = ra - rc, dB = rb - rc;
        float Gx = U0 * dA + U1 * dB;
        float Gy = V0 * dA + V1 * dB;
        float Gc = rc + W0 * dA + W1 * dB;
        e0 = make_float4(U0, V0, W0, fabsf(U0) + fabsf(V0));
        e1 = make_float4(U1, V1, W1, fabsf(U1) + fabsf(V1));
        e2 = make_float4(U2, V2, W2, fabsf(U2) + fabsf(V2));
        gi = make_float4(Gx, Gy, Gc, 0.f);
        bb = make_float4(fminf(ax, fminf(bx, cx)), fmaxf(ax, fmaxf(bx, cx)),
                         fminf(ay, fminf(by, cy)), fmaxf(ay, fmaxf(by, cy)));
    }
    g_e0[gid] = e0; g_e1[gid] = e1; g_e2[gid] = e2;
    g_gi[gid] = gi; g_bbox[gid] = bb;
}

// ---------------- K3: bound + list build (classification happens ONCE) -------
// grid (16,16,B_): sweep 1 computes final occlusion bound L; sweep 2 emits
// compacted per-tile index lists pruned against L.
__global__ void __launch_bounds__(256) k_bound() {
    __shared__ float sred[256];
    __shared__ int   snp, snf;

    int b   = blockIdx.z;
    int tid = threadIdx.x;
    int tx  = blockIdx.x * TILE;
    int ty  = blockIdx.y * TILE;
    int til = (b * NTX + blockIdx.y) * NTX + blockIdx.x;

    float xlo = 2.0f * (tx +  0.5f) / 256.0f - 1.0f;
    float xhi = 2.0f * (tx + 15.5f) / 256.0f - 1.0f;
    float ylo = 2.0f * (ty +  0.5f) / 256.0f - 1.0f;
    float yhi = 2.0f * (ty + 15.5f) / 256.0f - 1.0f;
    float xc  = 0.5f * (xlo + xhi);
    float yc  = 0.5f * (ylo + yhi);

    const float4* e0p  = g_e0   + b * F_;
    const float4* e1p  = g_e1   + b * F_;
    const float4* e2p  = g_e2   + b * F_;
    const float4* gip  = g_gi   + b * F_;
    const float4* bbox = g_bbox + b * F_;

    // ---- sweep 1: final occlusion bound L ----
    float L = 0.f;
    for (int tI = tid; tI < F_; tI += 256) {
        float4 bb = bbox[tI];
        if (bb.x > xhi || bb.y < xlo || bb.z > yhi || bb.w < ylo) continue;
        float4 r0 = e0p[tI];
        float4 r1 = e1p[tI];
        float4 r2 = e2p[tI];
        float cv0 = fmaf(r0.x, xc, fmaf(r0.y, yc, r0.z));
        float cv1 = fmaf(r1.x, xc, fmaf(r1.y, yc, r1.z));
        float cv2 = fmaf(r2.x, xc, fmaf(r2.y, yc, r2.z));
        float E0 = r0.w * HX, E1 = r1.w * HX, E2 = r2.w * HX;
        float me0 = fmaf(E0, 2e-6f, 1e-6f);
        float me1 = fmaf(E1, 2e-6f, 1e-6f);
        float me2 = fmaf(E2, 2e-6f, 1e-6f);
        if ((cv0 - E0 > me0) && (cv1 - E1 > me1) && (cv2 - E2 > me2)) {
            float4 gi = gip[tI];
            float ivc = fmaf(gi.x, xc, fmaf(gi.y, yc, gi.z));
            float Ei  = (fabsf(gi.x) + fabsf(gi.y)) * HX;
            L = fmaxf(L, ivc - Ei);
        }
    }
    sred[tid] = L;
    __syncthreads();
    for (int s = 128; s > 0; s >>= 1) {
        if (tid < s) sred[tid] = fmaxf(sred[tid], sred[tid + s]);
        __syncthreads();
    }
    if (tid == 0) { snp = 0; snf = 0; }
    __syncthreads();
    L = sred[0] - 2e-5f;

    // ---- sweep 2: classify with final L, emit index lists ----
    int* pl = g_plist + til * F_;
    int* fl = g_flist + til * F_;
    for (int tI = tid; tI < F_; tI += 256) {
        float4 bb = bbox[tI];
        if (bb.x > xhi || bb.y < xlo || bb.z > yhi || bb.w < ylo) continue;
        float4 r0 = e0p[tI];
        float4 r1 = e1p[tI];
        float4 r2 = e2p[tI];
        float cv0 = fmaf(r0.x, xc, fmaf(r0.y, yc, r0.z));
        float cv1 = fmaf(r1.x, xc, fmaf(r1.y, yc, r1.z));
        float cv2 = fmaf(r2.x, xc, fmaf(r2.y, yc, r2.z));
        float E0 = r0.w * HX, E1 = r1.w * HX, E2 = r2.w * HX;
        float me0 = fmaf(E0, 2e-6f, 1e-6f);
        float me1 = fmaf(E1, 2e-6f, 1e-6f);
        float me2 = fmaf(E2, 2e-6f, 1e-6f);

        bool rej = (cv0 + E0 < -me0) || (cv1 + E1 < -me1) || (cv2 + E2 < -me2);
        if (rej) continue;
        float4 gi = gip[tI];
        float ivc = fmaf(gi.x, xc, fmaf(gi.y, yc, gi.z));
        float Ei  = (fabsf(gi.x) + fabsf(gi.y)) * HX;
        if (ivc + Ei < L) continue;          // occluded: provably never wins
        bool full = (cv0 - E0 > me0) && (cv1 - E1 > me1) && (cv2 - E2 > me2);
        if (full) fl[atomicAdd(&snf, 1)] = tI;
        else      pl[atomicAdd(&snp, 1)] = tI;
    }
    __syncthreads();
    if (tid == 0) { g_np[til] = snp; g_nf[til] = snf; }
}

// ---------------- K4: pure streaming rasterizer (no classify, no barriers) ---
__global__ void __launch_bounds__(256) k_raster(float* __restrict__ dep,
                                                float* __restrict__ mask) {
    __shared__ float smx[256], smn[256];

    int b   = blockIdx.z;
    int tid = threadIdx.x;
    int tx  = blockIdx.x * TILE;
    int ty  = blockIdx.y * TILE;
    int til = (b * NTX + blockIdx.y) * NTX + blockIdx.x;
    int ix  = tx + (tid & 15);
    int iy  = ty + (tid >> 4);

    float x = 2.0f * (ix + 0.5f) / 256.0f - 1.0f;
    float y = 2.0f * (iy + 0.5f) / 256.0f - 1.0f;

    const float4* e0p = g_e0 + b * F_;
    const float4* e1p = g_e1 + b * F_;
    const float4* gip = g_gi + b * F_;
    const int* pl = g_plist + til * F_;
    const int* fl = g_flist + til * F_;
    int np = g_np[til], nf = g_nf[til];

    float m = 0.f;

    // partial list: uniform broadcast loads, 4 FFMA + sign-OR per triangle
    for (int j = 0; j < np; j++) {
        int tI = pl[j];
        float4 a  = e0p[tI];
        float4 e1 = e1p[tI];
        float4 gi = gip[tI];
        float w0 = fmaf(a.x,  x, fmaf(a.y,  y, a.z));
        float w1 = fmaf(e1.x, x, fmaf(e1.y, y, e1.z));
        float w2 = (1.0f - w0) - w1;
        float iv = fmaf(gi.x, x, fmaf(gi.y, y, gi.z));
        unsigned s = __float_as_uint(w0) | __float_as_uint(w1) | __float_as_uint(w2);
        m = fmaxf(m, __uint_as_float(__float_as_uint(iv) | (s & 0x80000000u)));
    }

    // full-accept list: interpolate inv and fmax
    for (int j = 0; j < nf; j++) {
        int tI = fl[j];
        float4 gi = gip[tI];
        m = fmaxf(m, fmaf(gi.x, x, fmaf(gi.y, y, gi.z)));
    }

    // fused z-pass: single writer per pixel
    bool  cov = m > 0.f;
    float z   = cov ? fminf(FARV, 1.0f / m) : FARV;
    int   pix = b * NPIX + iy * RW + ix;
    dep [pix] = z;
    mask[pix] = cov ? 1.0f : 0.0f;

    smx[tid] = (cov && z < FARV) ? z : 0.0f;
    smn[tid] = z;
    __syncthreads();
    for (int s = 128; s > 0; s >>= 1) {
        if (tid < s) {
            smx[tid] = fmaxf(smx[tid], smx[tid + s]);
            smn[tid] = fminf(smn[tid], smn[tid + s]);
        }
        __syncthreads();
    }
    if (tid == 0) {
        atomicMax(&g_mx[b], __float_as_uint(smx[0]));
        atomicMin(&g_mn[b], __float_as_uint(smn[0]));
    }
}

// ---------------- K5: depth normalization (float4, in place) -----------------
__global__ void __launch_bounds__(256) k_final(float* __restrict__ dep) {
    int idx4 = blockIdx.x * 256 + threadIdx.x;   // 0..65535
    int b    = idx4 >> 14;
    float mx = __uint_as_float(g_mx[b]);
    float rd = 1.0f / (mx - __uint_as_float(g_mn[b]) + 1e-4f);
    float4 z = reinterpret_cast<const float4*>(dep)[idx4];
    float4 o;
    o.x = fminf(fmaxf((mx - z.x) * rd, 0.0f), 1.0f);
    o.y = fminf(fmaxf((mx - z.y) * rd, 0.0f), 1.0f);
    o.z = fminf(fmaxf((mx - z.z) * rd, 0.0f), 1.0f);
    o.w = fminf(fmaxf((mx - z.w) * rd, 0.0f), 1.0f);
    reinterpret_cast<float4*>(dep)[idx4] = o;
}

// ---------------- launch ------------------------------------------------------
extern "C" void kernel_launch(void* const* d_in, const int* in_sizes, int n_in,
                              void* d_out, int out_size) {
    const float* vertices = (const float*)d_in[0];
    const int*   faces    = (const int*)  d_in[1];
    const float* intr     = (const float*)d_in[2];
    const float* R        = (const float*)d_in[3];
    const float* t        = (const float*)d_in[4];
    const float* dist     = (const float*)d_in[5];

    float* out  = (float*)d_out;
    float* dep  = out;
    float* mask = out + B_ * NPIX;

    dim3 tgrid(NTX, NTX, B_);
    k_project<<<(B_ * V_ + 255) / 256, 256>>>(vertices, intr, R, t, dist);
    k_setup<<<(B_ * F_ + 255) / 256, 256>>>(faces);
    k_bound<<<tgrid, 256>>>();
    k_raster<<<tgrid, 256>>>(dep, mask);
    k_final<<<256, 256>>>(dep);
}

// round 14
// speedup vs baseline: 1.2762x; 1.2762x over previous
#include <cuda_runtime.h>
#include <cuda_bf16.h>
#include <cstdint>

#define B_   4
#define V_   778
#define F_   1538
#define RW   256
#define NPIX (RW * RW)
#define FARV 10.0f
#define TILE 32
#define NTX  (RW / TILE)        // 8 tiles per axis
#define NTIL (B_ * NTX * NTX)   // 256 tiles total
#define HX   0.12109375f        // 32x32 tile half-extent in NDC (31px span/2 * 2/256)

// ---------------- scratch (static device globals; no allocation) -------------
__device__ float    g_uvz [B_ * V_ * 3];
__device__ float4   g_e0  [B_ * F_];   // U0,V0,W0,|U0|+|V0|
__device__ float4   g_e1  [B_ * F_];
__device__ float4   g_e2  [B_ * F_];
__device__ float4   g_gi  [B_ * F_];   // Gx,Gy,Gc,-
__device__ float4   g_bbox[B_ * F_];
__device__ float4   g_pA  [NTIL * F_]; // packed partial recs: U0,V0,W0,U1
__device__ float4   g_pB  [NTIL * F_]; //                      V1,W1,Gx,Gy
__device__ float    g_pC  [NTIL * F_]; //                      Gc
__device__ float4   g_fl  [NTIL * F_]; // full-accept recs: Gx,Gy,Gc,-
__device__ int      g_np  [NTIL];
__device__ int      g_nf  [NTIL];
__device__ unsigned g_mx  [B_];
__device__ unsigned g_mn  [B_];

// ---------------- K1: project vertices + clear reductions --------------------
__global__ void __launch_bounds__(256) k_project(const float* __restrict__ verts,
                                                 const float* __restrict__ intr,
                                                 const float* __restrict__ R,
                                                 const float* __restrict__ t,
                                                 const float* __restrict__ dist) {
    int idx = blockIdx.x * 256 + threadIdx.x;
    if (idx < B_) { g_mx[idx] = 0u; g_mn[idx] = __float_as_uint(FARV); }
    if (idx >= B_ * V_) return;
    int b = idx / V_;
    const float* p  = verts + idx * 3;
    const float* Rb = R    + b * 9;
    const float* tb = t    + b * 3;
    const float* Kb = intr + b * 9;
    const float* db = dist + b * 5;

    float px = p[0], py = p[1], pz = p[2];
    float x = Rb[0]*px + Rb[1]*py + Rb[2]*pz + tb[0];
    float y = Rb[3]*px + Rb[4]*py + Rb[5]*pz + tb[1];
    float z = Rb[6]*px + Rb[7]*py + Rb[8]*pz + tb[2];

    float zi = z + 1e-9f;
    float x_ = x / zi, y_ = y / zi;
    float k1 = db[0], k2 = db[1], p1 = db[2], p2 = db[3], k3 = db[4];
    float r2 = x_*x_ + y_*y_;
    float radial = 1.0f + k1*r2 + k2*r2*r2 + k3*r2*r2*r2;
    float x2 = x_*radial + 2.0f*p1*x_*y_ + p2*(r2 + 2.0f*x_*x_);
    float y2 = y_*radial + p1*(r2 + 2.0f*y_*y_) + 2.0f*p2*x_*y_;
    float u  = Kb[0]*x2 + Kb[1]*y2 + Kb[2];
    float vv = Kb[3]*x2 + Kb[4]*y2 + Kb[5];
    vv = 256.0f - vv;
    u  = 2.0f * (u  - 128.0f) / 256.0f;
    vv = 2.0f * (vv - 128.0f) / 256.0f;

    g_uvz[idx*3 + 0] = u;
    g_uvz[idx*3 + 1] = vv;
    g_uvz[idx*3 + 2] = z;
}

// ---------------- K2: triangle setup -----------------------------------------
__global__ void __launch_bounds__(256) k_setup(const int* __restrict__ faces) {
    int gid = blockIdx.x * 256 + threadIdx.x;
    if (gid >= B_ * F_) return;
    int b = gid / F_;

    int base = gid * 3;
    int i0 = faces[base + 0], i1 = faces[base + 1], i2 = faces[base + 2];

    const float* va = g_uvz + (b * V_ + i0) * 3;
    const float* vb = g_uvz + (b * V_ + i1) * 3;
    const float* vc = g_uvz + (b * V_ + i2) * 3;
    float ax = va[0], ay = va[1], az = va[2];
    float bx = vb[0], by = vb[1], bz = vb[2];
    float cx = vc[0], cy = vc[1], cz = vc[2];

    float den = (bx - ax) * (cy - ay) - (by - ay) * (cx - ax);
    bool ok = (fabsf(den) > 1e-8f) && (az > 1e-8f) && (bz > 1e-8f) && (cz > 1e-8f);

    float4 e0, e1, e2, gi, bb;
    if (!ok) {
        e0 = make_float4(0.f, 0.f, -1e30f, 0.f);
        e1 = make_float4(0.f, 0.f, 0.f, 0.f);
        e2 = make_float4(0.f, 0.f, 0.f, 0.f);
        gi = make_float4(0.f, 0.f, 0.f, 0.f);
        bb = make_float4(2e30f, -2e30f, 2e30f, -2e30f);
    } else {
        float id = 1.0f / den;
        float U0 = (by - cy) * id, V0 = (cx - bx) * id;
        float W0 = -(U0 * cx + V0 * cy);
        float U1 = (cy - ay) * id, V1 = (ax - cx) * id;
        float W1 = -(U1 * cx + V1 * cy);
        float U2 = -(U0 + U1), V2 = -(V0 + V1), W2 = 1.0f - W0 - W1;
        float ra = 1.0f / az, rb = 1.0f / bz, rc = 1.0f / cz;
        float dA = ra - rc, dB = rb - rc;
        float Gx = U0 * dA + U1 * dB;
        float Gy = V0 * dA + V1 * dB;
        float Gc = rc + W0 * dA + W1 * dB;
        e0 = make_float4(U0, V0, W0, fabsf(U0) + fabsf(V0));
        e1 = make_float4(U1, V1, W1, fabsf(U1) + fabsf(V1));
        e2 = make_float4(U2, V2, W2, fabsf(U2) + fabsf(V2));
        gi = make_float4(Gx, Gy, Gc, 0.f);
        bb = make_float4(fminf(ax, fminf(bx, cx)), fmaxf(ax, fmaxf(bx, cx)),
                         fminf(ay, fminf(by, cy)), fmaxf(ay, fmaxf(by, cy)));
    }
    g_e0[gid] = e0; g_e1[gid] = e1; g_e2[gid] = e2;
    g_gi[gid] = gi; g_bbox[gid] = bb;
}

// ---------------- K3: bound (cheap seed sweep) + single classification -------
// grid (8,8,B_): 32x32 tiles. Sweep 1: containment-prechecked L seed.
// Sweep 2: classify ONCE with final L, emit packed data records.
__global__ void __launch_bounds__(256) k_bound() {
    __shared__ float sred[256];
    __shared__ int   snp, snf;

    int b   = blockIdx.z;
    int tid = threadIdx.x;
    int tx  = blockIdx.x * TILE;
    int ty  = blockIdx.y * TILE;
    int til = (b * NTX + blockIdx.y) * NTX + blockIdx.x;

    float xlo = 2.0f * (tx +  0.5f) / 256.0f - 1.0f;
    float xhi = 2.0f * (tx + 31.5f) / 256.0f - 1.0f;
    float ylo = 2.0f * (ty +  0.5f) / 256.0f - 1.0f;
    float yhi = 2.0f * (ty + 31.5f) / 256.0f - 1.0f;
    float xc  = 0.5f * (xlo + xhi);
    float yc  = 0.5f * (ylo + yhi);

    const float4* e0p  = g_e0   + b * F_;
    const float4* e1p  = g_e1   + b * F_;
    const float4* e2p  = g_e2   + b * F_;
    const float4* gip  = g_gi   + b * F_;
    const float4* bbox = g_bbox + b * F_;

    // ---- sweep 1 (cheap): L from containment-prechecked full-accept tris ----
    float L = 0.f;
    for (int tI = tid; tI < F_; tI += 256) {
        float4 bb = bbox[tI];
        // necessary condition for full-accept: tile contained in bbox
        if (bb.x > xlo || bb.y < xhi || bb.z > ylo || bb.w < yhi) continue;
        float4 r0 = e0p[tI];
        float4 r1 = e1p[tI];
        float4 r2 = e2p[tI];
        float cv0 = fmaf(r0.x, xc, fmaf(r0.y, yc, r0.z));
        float cv1 = fmaf(r1.x, xc, fmaf(r1.y, yc, r1.z));
        float cv2 = fmaf(r2.x, xc, fmaf(r2.y, yc, r2.z));
        float E0 = r0.w * HX, E1 = r1.w * HX, E2 = r2.w * HX;
        float me0 = fmaf(E0, 2e-6f, 1e-6f);
        float me1 = fmaf(E1, 2e-6f, 1e-6f);
        float me2 = fmaf(E2, 2e-6f, 1e-6f);
        if ((cv0 - E0 > me0) && (cv1 - E1 > me1) && (cv2 - E2 > me2)) {
            float4 gi = gip[tI];
            float ivc = fmaf(gi.x, xc, fmaf(gi.y, yc, gi.z));
            float Ei  = (fabsf(gi.x) + fabsf(gi.y)) * HX;
            L = fmaxf(L, ivc - Ei);
        }
    }
    sred[tid] = L;
    __syncthreads();
    for (int s = 128; s > 0; s >>= 1) {
        if (tid < s) sred[tid] = fmaxf(sred[tid], sred[tid + s]);
        __syncthreads();
    }
    if (tid == 0) { snp = 0; snf = 0; }
    __syncthreads();
    L = sred[0] - 2e-5f;

    // ---- sweep 2: single classification, emit packed records ----
    float4* pA = g_pA + til * F_;
    float4* pB = g_pB + til * F_;
    float*  pC = g_pC + til * F_;
    float4* fl = g_fl + til * F_;
    for (int tI = tid; tI < F_; tI += 256) {
        float4 bb = bbox[tI];
        if (bb.x > xhi || bb.y < xlo || bb.z > yhi || bb.w < ylo) continue;
        float4 r0 = e0p[tI];
        float4 r1 = e1p[tI];
        float4 r2 = e2p[tI];
        float cv0 = fmaf(r0.x, xc, fmaf(r0.y, yc, r0.z));
        float cv1 = fmaf(r1.x, xc, fmaf(r1.y, yc, r1.z));
        float cv2 = fmaf(r2.x, xc, fmaf(r2.y, yc, r2.z));
        float E0 = r0.w * HX, E1 = r1.w * HX, E2 = r2.w * HX;
        float me0 = fmaf(E0, 2e-6f, 1e-6f);
        float me1 = fmaf(E1, 2e-6f, 1e-6f);
        float me2 = fmaf(E2, 2e-6f, 1e-6f);

        bool rej = (cv0 + E0 < -me0) || (cv1 + E1 < -me1) || (cv2 + E2 < -me2);
        if (rej) continue;
        float4 gi = gip[tI];
        float ivc = fmaf(gi.x, xc, fmaf(gi.y, yc, gi.z));
        float Ei  = (fabsf(gi.x) + fabsf(gi.y)) * HX;
        if (ivc + Ei < L) continue;          // occluded: provably never wins
        bool full = (cv0 - E0 > me0) && (cv1 - E1 > me1) && (cv2 - E2 > me2);
        if (full) {
            fl[atomicAdd(&snf, 1)] = gi;
        } else {
            int k = atomicAdd(&snp, 1);
            pA[k] = make_float4(r0.x, r0.y, r0.z, r1.x);
            pB[k] = make_float4(r1.y, r1.z, gi.x, gi.y);
            pC[k] = gi.z;
        }
    }
    __syncthreads();
    if (tid == 0) { g_np[til] = snp; g_nf[til] = snf; }
}

// ---------------- K4: streaming rasterizer (shared-staged, no classify) ------
// grid (8,8,B_): 32x32 px, 256 threads, 4 consecutive px per thread.
__global__ void __launch_bounds__(256) k_raster(float* __restrict__ dep,
                                                float* __restrict__ mask) {
    __shared__ float4 sA[256], sB[256];
    __shared__ float  sC[256];
    __shared__ float  smx[256], smn[256];

    int b   = blockIdx.z;
    int tid = threadIdx.x;
    int tx  = blockIdx.x * TILE;
    int ty  = blockIdx.y * TILE;
    int til = (b * NTX + blockIdx.y) * NTX + blockIdx.x;

    int row = tid >> 3;              // 0..31
    int xg  = tid & 7;               // 0..7
    int ix0 = tx + xg * 4;
    int iy  = ty + row;

    float y  = 2.0f * (iy + 0.5f) / 256.0f - 1.0f;
    float x0 = 2.0f * (ix0 + 0.5f) / 256.0f - 1.0f;
    float x1 = 2.0f * (ix0 + 1.5f) / 256.0f - 1.0f;
    float x2 = 2.0f * (ix0 + 2.5f) / 256.0f - 1.0f;
    float x3 = 2.0f * (ix0 + 3.5f) / 256.0f - 1.0f;

    const float4* pA = g_pA + til * F_;
    const float4* pB = g_pB + til * F_;
    const float*  pC = g_pC + til * F_;
    const float4* fl = g_fl + til * F_;
    int np = g_np[til], nf = g_nf[til];

    float m0 = 0.f, m1 = 0.f, m2 = 0.f, m3 = 0.f;

    // ---- partial records, staged through shared in chunks of 256 ----
    for (int c0 = 0; c0 < np; c0 += 256) {
        int j = c0 + tid;
        __syncthreads();
        if (j < np) { sA[tid] = pA[j]; sB[tid] = pB[j]; sC[tid] = pC[j]; }
        __syncthreads();
        int n = min(256, np - c0);
        for (int k = 0; k < n; k++) {
            float4 a = sA[k];
            float4 c = sB[k];
            float gc = sC[k];
            float ty0 = fmaf(a.y, y, a.z);
            float ty1 = fmaf(c.x, y, c.y);
            float tyi = fmaf(c.w, y, gc);
            {
                float w0 = fmaf(a.x, x0, ty0), w1 = fmaf(a.w, x0, ty1);
                float w2 = (1.0f - w0) - w1;
                float iv = fmaf(c.z, x0, tyi);
                unsigned s = __float_as_uint(w0) | __float_as_uint(w1) | __float_as_uint(w2);
                m0 = fmaxf(m0, __uint_as_float(__float_as_uint(iv) | (s & 0x80000000u)));
            }
            {
                float w0 = fmaf(a.x, x1, ty0), w1 = fmaf(a.w, x1, ty1);
                float w2 = (1.0f - w0) - w1;
                float iv = fmaf(c.z, x1, tyi);
                unsigned s = __float_as_uint(w0) | __float_as_uint(w1) | __float_as_uint(w2);
                m1 = fmaxf(m1, __uint_as_float(__float_as_uint(iv) | (s & 0x80000000u)));
            }
            {
                float w0 = fmaf(a.x, x2, ty0), w1 = fmaf(a.w, x2, ty1);
                float w2 = (1.0f - w0) - w1;
                float iv = fmaf(c.z, x2, tyi);
                unsigned s = __float_as_uint(w0) | __float_as_uint(w1) | __float_as_uint(w2);
                m2 = fmaxf(m2, __uint_as_float(__float_as_uint(iv) | (s & 0x80000000u)));
            }
            {
                float w0 = fmaf(a.x, x3, ty0), w1 = fmaf(a.w, x3, ty1);
                float w2 = (1.0f - w0) - w1;
                float iv = fmaf(c.z, x3, tyi);
                unsigned s = __float_as_uint(w0) | __float_as_uint(w1) | __float_as_uint(w2);
                m3 = fmaxf(m3, __uint_as_float(__float_as_uint(iv) | (s & 0x80000000u)));
            }
        }
    }

    // ---- full-accept records, staged through shared ----
    for (int c0 = 0; c0 < nf; c0 += 256) {
        int j = c0 + tid;
        __syncthreads();
        if (j < nf) sA[tid] = fl[j];
        __syncthreads();
        int n = min(256, nf - c0);
        #pragma unroll 2
        for (int k = 0; k < n; k++) {
            float4 f = sA[k];
            float tyi = fmaf(f.y, y, f.z);
            m0 = fmaxf(m0, fmaf(f.x, x0, tyi));
            m1 = fmaxf(m1, fmaf(f.x, x1, tyi));
            m2 = fmaxf(m2, fmaf(f.x, x2, tyi));
            m3 = fmaxf(m3, fmaf(f.x, x3, tyi));
        }
    }

    // ---- fused z-pass: single writer, float4 stores ----
    float z0 = m0 > 0.f ? fminf(FARV, 1.0f / m0) : FARV;
    float z1 = m1 > 0.f ? fminf(FARV, 1.0f / m1) : FARV;
    float z2 = m2 > 0.f ? fminf(FARV, 1.0f / m2) : FARV;
    float z3 = m3 > 0.f ? fminf(FARV, 1.0f / m3) : FARV;

    int pix = b * NPIX + iy * RW + ix0;
    reinterpret_cast<float4*>(dep  + pix)[0] = make_float4(z0, z1, z2, z3);
    reinterpret_cast<float4*>(mask + pix)[0] = make_float4(m0 > 0.f ? 1.f : 0.f,
                                                           m1 > 0.f ? 1.f : 0.f,
                                                           m2 > 0.f ? 1.f : 0.f,
                                                           m3 > 0.f ? 1.f : 0.f);
    float fx0 = (m0 > 0.f && z0 < FARV) ? z0 : 0.f;
    float fx1 = (m1 > 0.f && z1 < FARV) ? z1 : 0.f;
    float fx2 = (m2 > 0.f && z2 < FARV) ? z2 : 0.f;
    float fx3 = (m3 > 0.f && z3 < FARV) ? z3 : 0.f;

    __syncthreads();
    smx[tid] = fmaxf(fmaxf(fx0, fx1), fmaxf(fx2, fx3));
    smn[tid] = fminf(fminf(z0, z1), fminf(z2, z3));
    __syncthreads();
    for (int s = 128; s > 0; s >>= 1) {
        if (tid < s) {
            smx[tid] = fmaxf(smx[tid], smx[tid + s]);
            smn[tid] = fminf(smn[tid], smn[tid + s]);
        }
        __syncthreads();
    }
    if (tid == 0) {
        atomicMax(&g_mx[b], __float_as_uint(smx[0]));
        atomicMin(&g_mn[b], __float_as_uint(smn[0]));
    }
}

// ---------------- K5: depth normalization (float4, in place) -----------------
__global__ void __launch_bounds__(256) k_final(float* __restrict__ dep) {
    int idx4 = blockIdx.x * 256 + threadIdx.x;   // 0..65535
    int b    = idx4 >> 14;
    float mx = __uint_as_float(g_mx[b]);
    float rd = 1.0f / (mx - __uint_as_float(g_mn[b]) + 1e-4f);
    float4 z = reinterpret_cast<const float4*>(dep)[idx4];
    float4 o;
    o.x = fminf(fmaxf((mx - z.x) * rd, 0.0f), 1.0f);
    o.y = fminf(fmaxf((mx - z.y) * rd, 0.0f), 1.0f);
    o.z = fminf(fmaxf((mx - z.z) * rd, 0.0f), 1.0f);
    o.w = fminf(fmaxf((mx - z.w) * rd, 0.0f), 1.0f);
    reinterpret_cast<float4*>(dep)[idx4] = o;
}

// ---------------- launch ------------------------------------------------------
extern "C" void kernel_launch(void* const* d_in, const int* in_sizes, int n_in,
                              void* d_out, int out_size) {
    const float* vertices = (const float*)d_in[0];
    const int*   faces    = (const int*)  d_in[1];
    const float* intr     = (const float*)d_in[2];
    const float* R        = (const float*)d_in[3];
    const float* t        = (const float*)d_in[4];
    const float* dist     = (const float*)d_in[5];

    float* out  = (float*)d_out;
    float* dep  = out;
    float* mask = out + B_ * NPIX;

    dim3 tgrid(NTX, NTX, B_);
    k_project<<<(B_ * V_ + 255) / 256, 256>>>(vertices, intr, R, t, dist);
    k_setup<<<(B_ * F_ + 255) / 256, 256>>>(faces);
    k_bound<<<tgrid, 256>>>();
    k_raster<<<tgrid, 256>>>(dep, mask);
    k_final<<<256, 256>>>(dep);
}

// round 15
// speedup vs baseline: 1.3523x; 1.0596x over previous
#include <cuda_runtime.h>
#include <cuda_bf16.h>
#include <cstdint>

#define B_   4
#define V_   778
#define F_   1538
#define RW   256
#define NPIX (RW * RW)
#define FARV 10.0f
#define TILE 32
#define NTX  (RW / TILE)        // 8 tiles per axis
#define NTIL (B_ * NTX * NTX)   // 256 tiles total
#define HX   0.12109375f        // 32x32 tile half-extent in NDC (31px span/2 * 2/256)

// ---------------- scratch (static device globals; no allocation) -------------
__device__ float    g_uvz [B_ * V_ * 3];
__device__ float4   g_e0  [B_ * F_];   // U0,V0,W0,|U0|+|V0|
__device__ float4   g_e1  [B_ * F_];
__device__ float4   g_e2  [B_ * F_];
__device__ float4   g_gi  [B_ * F_];   // Gx,Gy,Gc,-
__device__ float4   g_bbox[B_ * F_];
__device__ float4   g_pA  [NTIL * F_]; // packed partial recs: U0,V0,W0,U1
__device__ float4   g_pB  [NTIL * F_]; //                      V1,W1,Gx,Gy
__device__ float    g_pC  [NTIL * F_]; //                      Gc
__device__ float4   g_fl  [NTIL * F_]; // full-accept recs: Gx,Gy,Gc,-
__device__ int      g_np  [NTIL];
__device__ int      g_nf  [NTIL];
__device__ unsigned g_mx  [B_];
__device__ unsigned g_mn  [B_];

// ---------------- K1: project vertices + clear reductions --------------------
__global__ void __launch_bounds__(256) k_project(const float* __restrict__ verts,
                                                 const float* __restrict__ intr,
                                                 const float* __restrict__ R,
                                                 const float* __restrict__ t,
                                                 const float* __restrict__ dist) {
    int idx = blockIdx.x * 256 + threadIdx.x;
    if (idx < B_) { g_mx[idx] = 0u; g_mn[idx] = __float_as_uint(FARV); }
    if (idx >= B_ * V_) return;
    int b = idx / V_;
    const float* p  = verts + idx * 3;
    const float* Rb = R    + b * 9;
    const float* tb = t    + b * 3;
    const float* Kb = intr + b * 9;
    const float* db = dist + b * 5;

    float px = p[0], py = p[1], pz = p[2];
    float x = Rb[0]*px + Rb[1]*py + Rb[2]*pz + tb[0];
    float y = Rb[3]*px + Rb[4]*py + Rb[5]*pz + tb[1];
    float z = Rb[6]*px + Rb[7]*py + Rb[8]*pz + tb[2];

    float zi = z + 1e-9f;
    float x_ = x / zi, y_ = y / zi;
    float k1 = db[0], k2 = db[1], p1 = db[2], p2 = db[3], k3 = db[4];
    float r2 = x_*x_ + y_*y_;
    float radial = 1.0f + k1*r2 + k2*r2*r2 + k3*r2*r2*r2;
    float x2 = x_*radial + 2.0f*p1*x_*y_ + p2*(r2 + 2.0f*x_*x_);
    float y2 = y_*radial + p1*(r2 + 2.0f*y_*y_) + 2.0f*p2*x_*y_;
    float u  = Kb[0]*x2 + Kb[1]*y2 + Kb[2];
    float vv = Kb[3]*x2 + Kb[4]*y2 + Kb[5];
    vv = 256.0f - vv;
    u  = 2.0f * (u  - 128.0f) / 256.0f;
    vv = 2.0f * (vv - 128.0f) / 256.0f;

    g_uvz[idx*3 + 0] = u;
    g_uvz[idx*3 + 1] = vv;
    g_uvz[idx*3 + 2] = z;
}

// ---------------- K2: triangle setup -----------------------------------------
__global__ void __launch_bounds__(256) k_setup(const int* __restrict__ faces) {
    int gid = blockIdx.x * 256 + threadIdx.x;
    if (gid >= B_ * F_) return;
    int b = gid / F_;

    int base = gid * 3;
    int i0 = faces[base + 0], i1 = faces[base + 1], i2 = faces[base + 2];

    const float* va = g_uvz + (b * V_ + i0) * 3;
    const float* vb = g_uvz + (b * V_ + i1) * 3;
    const float* vc = g_uvz + (b * V_ + i2) * 3;
    float ax = va[0], ay = va[1], az = va[2];
    float bx = vb[0], by = vb[1], bz = vb[2];
    float cx = vc[0], cy = vc[1], cz = vc[2];

    float den = (bx - ax) * (cy - ay) - (by - ay) * (cx - ax);
    bool ok = (fabsf(den) > 1e-8f) && (az > 1e-8f) && (bz > 1e-8f) && (cz > 1e-8f);

    float4 e0, e1, e2, gi, bb;
    if (!ok) {
        e0 = make_float4(0.f, 0.f, -1e30f, 0.f);
        e1 = make_float4(0.f, 0.f, 0.f, 0.f);
        e2 = make_float4(0.f, 0.f, 0.f, 0.f);
        gi = make_float4(0.f, 0.f, 0.f, 0.f);
        bb = make_float4(2e30f, -2e30f, 2e30f, -2e30f);
    } else {
        float id = 1.0f / den;
        float U0 = (by - cy) * id, V0 = (cx - bx) * id;
        float W0 = -(U0 * cx + V0 * cy);
        float U1 = (cy - ay) * id, V1 = (ax - cx) * id;
        float W1 = -(U1 * cx + V1 * cy);
        float U2 = -(U0 + U1), V2 = -(V0 + V1), W2 = 1.0f - W0 - W1;
        float ra = 1.0f / az, rb = 1.0f / bz, rc = 1.0f / cz;
        float dA = ra - rc, dB = rb - rc;
        float Gx = U0 * dA + U1 * dB;
        float Gy = V0 * dA + V1 * dB;
        float Gc = rc + W0 * dA + W1 * dB;
        e0 = make_float4(U0, V0, W0, fabsf(U0) + fabsf(V0));
        e1 = make_float4(U1, V1, W1, fabsf(U1) + fabsf(V1));
        e2 = make_float4(U2, V2, W2, fabsf(U2) + fabsf(V2));
        gi = make_float4(Gx, Gy, Gc, 0.f);
        bb = make_float4(fminf(ax, fminf(bx, cx)), fmaxf(ax, fmaxf(bx, cx)),
                         fminf(ay, fminf(by, cy)), fmaxf(ay, fmaxf(by, cy)));
    }
    g_e0[gid] = e0; g_e1[gid] = e1; g_e2[gid] = e2;
    g_gi[gid] = gi; g_bbox[gid] = bb;
}

// ---------------- K3: bound (cheap seed sweep) + single classification -------
// grid (8,8,B_): 32x32 tiles. Sweep 1: containment-prechecked L seed.
// Sweep 2: classify ONCE with final L, emit packed data records.
__global__ void __launch_bounds__(256) k_bound() {
    __shared__ float sred[256];
    __shared__ int   snp, snf;

    int b   = blockIdx.z;
    int tid = threadIdx.x;
    int tx  = blockIdx.x * TILE;
    int ty  = blockIdx.y * TILE;
    int til = (b * NTX + blockIdx.y) * NTX + blockIdx.x;

    float xlo = 2.0f * (tx +  0.5f) / 256.0f - 1.0f;
    float xhi = 2.0f * (tx + 31.5f) / 256.0f - 1.0f;
    float ylo = 2.0f * (ty +  0.5f) / 256.0f - 1.0f;
    float yhi = 2.0f * (ty + 31.5f) / 256.0f - 1.0f;
    float xc  = 0.5f * (xlo + xhi);
    float yc  = 0.5f * (ylo + yhi);

    const float4* e0p  = g_e0   + b * F_;
    const float4* e1p  = g_e1   + b * F_;
    const float4* e2p  = g_e2   + b * F_;
    const float4* gip  = g_gi   + b * F_;
    const float4* bbox = g_bbox + b * F_;

    // ---- sweep 1 (cheap): L from containment-prechecked full-accept tris ----
    float L = 0.f;
    for (int tI = tid; tI < F_; tI += 256) {
        float4 bb = bbox[tI];
        // necessary condition for full-accept: tile contained in bbox
        if (bb.x > xlo || bb.y < xhi || bb.z > ylo || bb.w < yhi) continue;
        float4 r0 = e0p[tI];
        float4 r1 = e1p[tI];
        float4 r2 = e2p[tI];
        float cv0 = fmaf(r0.x, xc, fmaf(r0.y, yc, r0.z));
        float cv1 = fmaf(r1.x, xc, fmaf(r1.y, yc, r1.z));
        float cv2 = fmaf(r2.x, xc, fmaf(r2.y, yc, r2.z));
        float E0 = r0.w * HX, E1 = r1.w * HX, E2 = r2.w * HX;
        float me0 = fmaf(E0, 2e-6f, 1e-6f);
        float me1 = fmaf(E1, 2e-6f, 1e-6f);
        float me2 = fmaf(E2, 2e-6f, 1e-6f);
        if ((cv0 - E0 > me0) && (cv1 - E1 > me1) && (cv2 - E2 > me2)) {
            float4 gi = gip[tI];
            float ivc = fmaf(gi.x, xc, fmaf(gi.y, yc, gi.z));
            float Ei  = (fabsf(gi.x) + fabsf(gi.y)) * HX;
            L = fmaxf(L, ivc - Ei);
        }
    }
    sred[tid] = L;
    __syncthreads();
    for (int s = 128; s > 0; s >>= 1) {
        if (tid < s) sred[tid] = fmaxf(sred[tid], sred[tid + s]);
        __syncthreads();
    }
    if (tid == 0) { snp = 0; snf = 0; }
    __syncthreads();
    L = sred[0] - 2e-5f;

    // ---- sweep 2: single classification, emit packed records ----
    float4* pA = g_pA + til * F_;
    float4* pB = g_pB + til * F_;
    float*  pC = g_pC + til * F_;
    float4* fl = g_fl + til * F_;
    for (int tI = tid; tI < F_; tI += 256) {
        float4 bb = bbox[tI];
        if (bb.x > xhi || bb.y < xlo || bb.z > yhi || bb.w < ylo) continue;
        float4 r0 = e0p[tI];
        float4 r1 = e1p[tI];
        float4 r2 = e2p[tI];
        float cv0 = fmaf(r0.x, xc, fmaf(r0.y, yc, r0.z));
        float cv1 = fmaf(r1.x, xc, fmaf(r1.y, yc, r1.z));
        float cv2 = fmaf(r2.x, xc, fmaf(r2.y, yc, r2.z));
        float E0 = r0.w * HX, E1 = r1.w * HX, E2 = r2.w * HX;
        float me0 = fmaf(E0, 2e-6f, 1e-6f);
        float me1 = fmaf(E1, 2e-6f, 1e-6f);
        float me2 = fmaf(E2, 2e-6f, 1e-6f);

        bool rej = (cv0 + E0 < -me0) || (cv1 + E1 < -me1) || (cv2 + E2 < -me2);
        if (rej) continue;
        float4 gi = gip[tI];
        float ivc = fmaf(gi.x, xc, fmaf(gi.y, yc, gi.z));
        float Ei  = (fabsf(gi.x) + fabsf(gi.y)) * HX;
        if (ivc + Ei < L) continue;          // occluded: provably never wins
        bool full = (cv0 - E0 > me0) && (cv1 - E1 > me1) && (cv2 - E2 > me2);
        if (full) {
            fl[atomicAdd(&snf, 1)] = gi;
        } else {
            int k = atomicAdd(&snp, 1);
            pA[k] = make_float4(r0.x, r0.y, r0.z, r1.x);
            pB[k] = make_float4(r1.y, r1.z, gi.x, gi.y);
            pC[k] = gi.z;
        }
    }
    __syncthreads();
    if (tid == 0) { g_np[til] = snp; g_nf[til] = snf; }
}

// ---------------- K4: streaming rasterizer, 4 row-slab blocks per tile -------
// grid (8,8,B_*4): z = b*4 + slab. Block covers 32 cols x 8 rows, 1 px/thread.
__global__ void __launch_bounds__(256) k_raster(float* __restrict__ dep,
                                                float* __restrict__ mask) {
    __shared__ float4 sA[256], sB[256];
    __shared__ float  sC[256];
    __shared__ float  smx[256], smn[256];

    int bz   = blockIdx.z;
    int b    = bz >> 2;
    int slab = bz & 3;
    int tid  = threadIdx.x;
    int tx   = blockIdx.x * TILE;
    int ty   = blockIdx.y * TILE;
    int til  = (b * NTX + blockIdx.y) * NTX + blockIdx.x;

    int ix = tx + (tid & 31);
    int iy = ty + slab * 8 + (tid >> 5);

    float x = 2.0f * (ix + 0.5f) / 256.0f - 1.0f;
    float y = 2.0f * (iy + 0.5f) / 256.0f - 1.0f;

    const float4* pA = g_pA + til * F_;
    const float4* pB = g_pB + til * F_;
    const float*  pC = g_pC + til * F_;
    const float4* fl = g_fl + til * F_;
    int np = g_np[til], nf = g_nf[til];

    float m = 0.f;

    // ---- partial records, staged through shared in chunks of 256 ----
    for (int c0 = 0; c0 < np; c0 += 256) {
        int j = c0 + tid;
        __syncthreads();
        if (j < np) { sA[tid] = pA[j]; sB[tid] = pB[j]; sC[tid] = pC[j]; }
        __syncthreads();
        int n = min(256, np - c0);
        for (int k = 0; k < n; k++) {
            float4 a = sA[k];
            float4 c = sB[k];
            float gc = sC[k];
            float w0 = fmaf(a.x, x, fmaf(a.y, y, a.z));
            float w1 = fmaf(a.w, x, fmaf(c.x, y, c.y));
            float w2 = (1.0f - w0) - w1;
            float iv = fmaf(c.z, x, fmaf(c.w, y, gc));
            unsigned s = __float_as_uint(w0) | __float_as_uint(w1) | __float_as_uint(w2);
            m = fmaxf(m, __uint_as_float(__float_as_uint(iv) | (s & 0x80000000u)));
        }
    }

    // ---- full-accept records, staged through shared ----
    for (int c0 = 0; c0 < nf; c0 += 256) {
        int j = c0 + tid;
        __syncthreads();
        if (j < nf) sA[tid] = fl[j];
        __syncthreads();
        int n = min(256, nf - c0);
        #pragma unroll 2
        for (int k = 0; k < n; k++) {
            float4 f = sA[k];
            m = fmaxf(m, fmaf(f.x, x, fmaf(f.y, y, f.z)));
        }
    }

    // ---- fused z-pass: single writer per pixel ----
    bool  cov = m > 0.f;
    float z   = cov ? fminf(FARV, 1.0f / m) : FARV;
    int   pix = b * NPIX + iy * RW + ix;
    dep [pix] = z;
    mask[pix] = cov ? 1.0f : 0.0f;

    smx[tid] = (cov && z < FARV) ? z : 0.0f;
    smn[tid] = z;
    __syncthreads();
    for (int s = 128; s > 0; s >>= 1) {
        if (tid < s) {
            smx[tid] = fmaxf(smx[tid], smx[tid + s]);
            smn[tid] = fminf(smn[tid], smn[tid + s]);
        }
        __syncthreads();
    }
    if (tid == 0) {
        atomicMax(&g_mx[b], __float_as_uint(smx[0]));
        atomicMin(&g_mn[b], __float_as_uint(smn[0]));
    }
}

// ---------------- K5: depth normalization (float4, in place) -----------------
__global__ void __launch_bounds__(256) k_final(float* __restrict__ dep) {
    int idx4 = blockIdx.x * 256 + threadIdx.x;   // 0..65535
    int b    = idx4 >> 14;
    float mx = __uint_as_float(g_mx[b]);
    float rd = 1.0f / (mx - __uint_as_float(g_mn[b]) + 1e-4f);
    float4 z = reinterpret_cast<const float4*>(dep)[idx4];
    float4 o;
    o.x = fminf(fmaxf((mx - z.x) * rd, 0.0f), 1.0f);
    o.y = fminf(fmaxf((mx - z.y) * rd, 0.0f), 1.0f);
    o.z = fminf(fmaxf((mx - z.z) * rd, 0.0f), 1.0f);
    o.w = fminf(fmaxf((mx - z.w) * rd, 0.0f), 1.0f);
    reinterpret_cast<float4*>(dep)[idx4] = o;
}

// ---------------- launch ------------------------------------------------------
extern "C" void kernel_launch(void* const* d_in, const int* in_sizes, int n_in,
                              void* d_out, int out_size) {
    const float* vertices = (const float*)d_in[0];
    const int*   faces    = (const int*)  d_in[1];
    const float* intr     = (const float*)d_in[2];
    const float* R        = (const float*)d_in[3];
    const float* t        = (const float*)d_in[4];
    const float* dist     = (const float*)d_in[5];

    float* out  = (float*)d_out;
    float* dep  = out;
    float* mask = out + B_ * NPIX;

    dim3 tgrid(NTX, NTX, B_);
    dim3 rgrid(NTX, NTX, B_ * 4);
    k_project<<<(B_ * V_ + 255) / 256, 256>>>(vertices, intr, R, t, dist);
    k_setup<<<(B_ * F_ + 255) / 256, 256>>>(faces);
    k_bound<<<tgrid, 256>>>();
    k_raster<<<rgrid, 256>>>(dep, mask);
    k_final<<<256, 256>>>(dep);
}